// round 14
// baseline (speedup 1.0000x reference)
#include <cuda_runtime.h>
#include <cuda_fp16.h>
#include <math.h>
#include <stdint.h>

// ---------------------------------------------------------------------------
// DecoderRNN: 240-step LSTM decoder, B=512, H=2048, OUT=165, NCLS=40
// R14: f16-ACCUMULATE mma.sync experiment. HMMA f16.f16.f16.f16 accumulators,
// promoted to f32 registers every 4 k-iters (K=128 chunks). If the legacy
// HMMA f16-acc path retires 2x faster than f32-acc, gates GEMM halves.
// Structure: R9/R10 persistent skeleton, 512 threads, 4-stage pipeline,
// loop-based stage loader (exact coverage for all tile shapes), dynamic
// tile fetch, 3 phases/step, fused LSTM cell, ping-pong X buffers.
// ---------------------------------------------------------------------------

#define BATCH   512
#define HID     2048
#define G4      8192
#define OUTD    165
#define NCLS    40
#define SEQL    240
#define WIH_COLS 330
#define KXP     2240        // 2048 (h) + 192 (out_prev pad)
#define NPAD2   192

#define ROWH    40          // smem row stride in halves (32 + 8 pad)
#define NTHREADS 512
#define STGB    ((128 + 128) * ROWH * 2)    // 20480 per slab (max shape)
#define NSTAGE  4
#define SMEM_REQ (NSTAGE * STGB)            // 81920

// ------------------------- device scratch ----------------------------------
__device__ __half d_Wcat[(size_t)G4 * KXP];     // interleaved rows n'=4k+g
__device__ __half d_Wfc1[(size_t)HID * HID];
__device__ __half d_Wfc2[(size_t)NPAD2 * HID];
__device__ float  d_gbias[NCLS * G4];           // interleaved cols
__device__ __half d_Xbuf[2][BATCH * KXP];       // ping-pong (h | out_prev)
__device__ float  d_cst[BATCH * HID];
__device__ __half d_t1[BATCH * HID];
__device__ unsigned g_arrive;
__device__ unsigned g_ctr[1024];                // per-epoch tile counters

// ------------------------- ONE setup kernel --------------------------------
#define NA      71680                       // G4*KXP/256
#define SB_FC1  (NA + 16384)
#define SB_FC2  (SB_FC1 + 1536)
#define SB_GB   (SB_FC2 + NCLS * 32)
#define SB_INIT (SB_GB + BATCH * 8)
#define SB_XPAD (SB_INIT + BATCH)
#define SB_TOT  (SB_XPAD + 4)
__global__ void setup_all(const float* __restrict__ inputs,
                          const float* __restrict__ W_enc, const float* __restrict__ b_enc,
                          const float* __restrict__ W_ih,  const float* __restrict__ b_ih,
                          const float* __restrict__ W_hh,  const float* __restrict__ b_hh,
                          const float* __restrict__ W_fc1,
                          const float* __restrict__ W_fc2,
                          const float* __restrict__ W_inh, const float* __restrict__ b_inh,
                          const float* __restrict__ W_inc, const float* __restrict__ b_inc) {
    int bid = blockIdx.x, tid = threadIdx.x;
    if (bid == 0 && tid == 0) g_arrive = 0;

    if (bid < NA) {
        size_t idx = (size_t)bid * 256 + tid;
        int np = (int)(idx / KXP), k = (int)(idx % KXP);
        int n = (np & 3) * HID + (np >> 2);       // interleave n'=4k+g
        float v = 0.f;
        if (k < HID)             v = W_hh[(size_t)n * HID + k];
        else if (k - HID < OUTD) v = W_ih[(size_t)n * WIH_COLS + (k - HID)];
        d_Wcat[idx] = __float2half(v);
    } else if (bid < SB_FC1) {
        size_t idx = (size_t)(bid - NA) * 256 + tid;
        d_Wfc1[idx] = __float2half(W_fc1[idx]);
    } else if (bid < SB_FC2) {
        size_t idx = (size_t)(bid - SB_FC1) * 256 + tid;
        int n = (int)(idx / HID), k = (int)(idx % HID);
        d_Wfc2[idx] = __float2half(n < OUTD ? W_fc2[(size_t)n * HID + k] : 0.f);
    } else if (bid < SB_GB) {
        int q = bid - SB_FC2;
        int cls = q >> 5;
        int n = (q & 31) * 256 + tid;
        __shared__ float enc[OUTD];
        if (tid < OUTD) enc[tid] = W_enc[tid * NCLS + cls] + b_enc[tid];
        __syncthreads();
        float a = b_ih[n] + b_hh[n];
        const float* wrow = W_ih + (size_t)n * WIH_COLS + OUTD;
        #pragma unroll 5
        for (int j = 0; j < OUTD; j++) a += wrow[j] * enc[j];
        int np = 4 * (n & (HID - 1)) + (n >> 11);
        d_gbias[cls * G4 + np] = a;
    } else if (bid < SB_INIT) {
        int q = bid - SB_GB;
        int b = q >> 3;
        int k = (q & 7) * 256 + tid;
        __shared__ float f0[OUTD];
        if (tid < OUTD) f0[tid] = inputs[b * OUTD + tid];
        __syncthreads();
        float ah = b_inh[k], ac = b_inc[k];
        const float* wh = W_inh + (size_t)k * OUTD;
        const float* wc = W_inc + (size_t)k * OUTD;
        #pragma unroll 5
        for (int j = 0; j < OUTD; j++) { ah += f0[j] * wh[j]; ac += f0[j] * wc[j]; }
        d_cst[b * HID + k] = ac;
        d_Xbuf[0][b * KXP + k] = __float2half(ah);
    } else if (bid < SB_XPAD) {
        int b = bid - SB_INIT;
        int j = tid;
        if (j < KXP - HID) {
            float v = (j < OUTD) ? inputs[b * OUTD + j] : 0.f;
            d_Xbuf[0][b * KXP + HID + j] = __float2half(v);
            if (j >= OUTD) d_Xbuf[1][b * KXP + HID + j] = __float2half(0.f);
        }
    } else {
        int i = (bid - SB_XPAD) * 256 + tid;
        if (i < 1024) g_ctr[i] = 0;
    }
}

// ------------------------- helpers -----------------------------------------
__device__ __forceinline__ void cpa16(uint32_t s, const void* g) {
    asm volatile("cp.async.cg.shared.global [%0], [%1], 16;" :: "r"(s), "l"(g));
}
__device__ __forceinline__ void cpa_commit() { asm volatile("cp.async.commit_group;"); }
template<int N> __device__ __forceinline__ void cpa_wait() {
    asm volatile("cp.async.wait_group %0;" :: "n"(N));
}
__device__ __forceinline__ float sigf(float x) {
    return __fdividef(1.f, 1.f + __expf(-x));
}
__device__ __forceinline__ float tanhf_(float x) {
    float e = __expf(-2.f * x);
    return __fdividef(1.f - e, 1.f + e);
}
__device__ __forceinline__ void grid_sync(unsigned nblocks, unsigned& ep) {
    __syncthreads();
    if (threadIdx.x == 0) {
        __threadfence();
        atomicAdd(&g_arrive, 1u);
        unsigned want = (ep + 1u) * nblocks;
        while (*(volatile unsigned*)&g_arrive < want) { __nanosleep(64); }
        __threadfence();
    }
    ep++;
    __syncthreads();
}
// f16-accumulate HMMA: D(f16x2 pair) = A*B + D
__device__ __forceinline__ void mma16(uint32_t& c0, uint32_t& c1,
                                      uint32_t a0, uint32_t a1, uint32_t a2,
                                      uint32_t a3, uint32_t b0, uint32_t b1) {
    asm volatile(
        "mma.sync.aligned.m16n8k16.row.col.f16.f16.f16.f16 "
        "{%0,%1}, {%2,%3,%4,%5}, {%6,%7}, {%0,%1};"
        : "+r"(c0), "+r"(c1)
        : "r"(a0), "r"(a1), "r"(a2), "r"(a3), "r"(b0), "r"(b1));
}

// ------------------------- GEMM tile (f16-acc mma.sync) --------------------
// C[BM,BN] = A[BM, 0:K] @ B[BN, 0:K]^T. 16 warps (2m x 8n); warp (BM/2)x(BN/8)
// 4-stage pipeline, 1 barrier/k-iter; f16 accumulators promoted to f32 every
// 4 k-iters (K=128 chunks). Loop loader covers any (BM+BN).
// MODE 0: gates (128x128, K=2240) + gbias + fused LSTM cell -> Xw, d_cst
// MODE 1: fc1   (64x128,  K=2048) + relu+bias -> d_t1
// MODE 2: fc2   (64x64,   K=2048) + bias -> out & Xw out_prev tail
template<int MODE, int BM, int BN>
__device__ void gemm_tile(int m0, int n0, int K,
                          const __half* __restrict__ Ag, int lda,
                          __half* __restrict__ Xw,
                          const int* __restrict__ labels,
                          const float* __restrict__ bias,
                          float* __restrict__ outp, int t,
                          uint32_t sa) {
    constexpr int WMr = BM / 2;
    constexpr int WNr = BN / 8;
    constexpr int MT  = WMr / 16;
    constexpr int NT  = WNr / 8;       // 2 (BN=128) or 1 (BN=64)
    constexpr int CH  = (BM + BN) * 4; // 16B chunks per stage

    const __half* Bg; int ldb;
    if (MODE == 1)      { Bg = d_Wfc1; ldb = HID; }
    else if (MODE == 2) { Bg = d_Wfc2; ldb = HID; }
    else                { Bg = d_Wcat; ldb = KXP; }
    const int nk = K / 32;

    const int tid  = threadIdx.x;
    const int lane = tid & 31;
    const int wid  = tid >> 5;
    const int wm   = wid & 1;
    const int wn   = wid >> 1;          // 0..7

    float    facc[MT][NT][4];
    uint32_t hacc[MT][NT][2];
    #pragma unroll
    for (int i = 0; i < MT; i++)
        #pragma unroll
        for (int j = 0; j < NT; j++) {
            #pragma unroll
            for (int k = 0; k < 4; k++) facc[i][j][k] = 0.f;
            hacc[i][j][0] = 0u; hacc[i][j][1] = 0u;
        }

    auto promote = [&]() {
        #pragma unroll
        for (int i = 0; i < MT; i++)
            #pragma unroll
            for (int j = 0; j < NT; j++) {
                float2 f0 = __half22float2(*(__half2*)&hacc[i][j][0]);
                float2 f1 = __half22float2(*(__half2*)&hacc[i][j][1]);
                facc[i][j][0] += f0.x; facc[i][j][1] += f0.y;
                facc[i][j][2] += f1.x; facc[i][j][3] += f1.y;
                hacc[i][j][0] = 0u; hacc[i][j][1] = 0u;
            }
    };

    auto load_stage = [&](int st, int kb) {
        const int ko = kb * 32;
        const uint32_t base = sa + (uint32_t)(st * STGB);
        #pragma unroll
        for (int c = tid; c < CH; c += NTHREADS) {
            int row = c >> 2;
            int k8  = (c & 3) * 8;
            const __half* g = (row < BM)
                ? Ag + (size_t)(m0 + row) * lda + ko + k8
                : Bg + (size_t)(n0 + row - BM) * ldb + ko + k8;
            cpa16(base + (uint32_t)((row * ROWH + k8) * 2), g);
        }
    };

    // ldmatrix lane bases (stage-relative)
    const uint32_t aOff = (uint32_t)(((wm * WMr + (lane & 15)) * ROWH
                                      + (lane >> 4) * 8) * 2);
    const uint32_t bOff4 = (uint32_t)(((BM + wn * WNr + (lane & 15)) * ROWH
                                       + (lane >> 4) * 8) * 2);
    const uint32_t bOff2 = (uint32_t)(((BM + wn * WNr + (lane & 7)) * ROWH
                                       + ((lane >> 3) & 1) * 8) * 2);

    load_stage(0, 0); cpa_commit();
    load_stage(1, 1); cpa_commit();
    load_stage(2, 2); cpa_commit();

    for (int kb = 0; kb < nk; kb++) {
        cpa_wait<2>();
        __syncthreads();
        if (kb + 3 < nk) load_stage((kb + 3) & 3, kb + 3);
        cpa_commit();

        const uint32_t stb = sa + (uint32_t)((kb & 3) * STGB);
        const uint32_t aS = stb + aOff;
        #pragma unroll
        for (int ks = 0; ks < 2; ks++) {
            uint32_t af[MT][4];
            #pragma unroll
            for (int mt = 0; mt < MT; mt++) {
                uint32_t ad = aS + (uint32_t)((mt * 16 * ROWH + ks * 16) * 2);
                asm volatile("ldmatrix.sync.aligned.m8n8.x4.shared.b16 "
                             "{%0,%1,%2,%3}, [%4];"
                             : "=r"(af[mt][0]), "=r"(af[mt][1]),
                               "=r"(af[mt][2]), "=r"(af[mt][3]) : "r"(ad));
            }
            uint32_t bb[NT][2];
            if constexpr (NT >= 2) {
                const uint32_t bS = stb + bOff4;
                #pragma unroll
                for (int np = 0; np < NT / 2; np++) {
                    uint32_t bd = bS + (uint32_t)((np * 16 * ROWH + ks * 16) * 2);
                    asm volatile("ldmatrix.sync.aligned.m8n8.x4.shared.b16 "
                                 "{%0,%1,%2,%3}, [%4];"
                                 : "=r"(bb[2*np][0]), "=r"(bb[2*np+1][0]),
                                   "=r"(bb[2*np][1]), "=r"(bb[2*np+1][1]) : "r"(bd));
                }
            } else {
                const uint32_t bS = stb + bOff2;
                uint32_t bd = bS + (uint32_t)((ks * 16) * 2);
                asm volatile("ldmatrix.sync.aligned.m8n8.x2.shared.b16 "
                             "{%0,%1}, [%2];"
                             : "=r"(bb[0][0]), "=r"(bb[0][1]) : "r"(bd));
            }
            #pragma unroll
            for (int nt = 0; nt < NT; nt++)
                #pragma unroll
                for (int mt = 0; mt < MT; mt++)
                    mma16(hacc[mt][nt][0], hacc[mt][nt][1],
                          af[mt][0], af[mt][1], af[mt][2], af[mt][3],
                          bb[nt][0], bb[nt][1]);
        }
        if ((kb & 3) == 3 || kb == nk - 1) promote();
    }
    cpa_wait<0>();

    // ---------------- epilogue (facc holds f32 results) ----------------
    const int r  = lane >> 2;
    const int c2 = (lane & 3) << 1;
    #pragma unroll
    for (int mt = 0; mt < MT; mt++) {
        int row0 = m0 + wm * WMr + mt * 16 + r;
        int row1 = row0 + 8;
        int lb0 = 0, lb1 = 0;
        if (MODE == 0) { lb0 = labels[row0]; lb1 = labels[row1]; }
        #pragma unroll
        for (int nt = 0; nt < NT; nt++) {
            int col0 = n0 + wn * WNr + nt * 8 + c2;
            float v00 = facc[mt][nt][0], v01 = facc[mt][nt][1];
            float v10 = facc[mt][nt][2], v11 = facc[mt][nt][3];
            if (MODE == 0) {
                v00 += d_gbias[lb0 * G4 + col0];
                v01 += d_gbias[lb0 * G4 + col0 + 1];
                v10 += d_gbias[lb1 * G4 + col0];
                v11 += d_gbias[lb1 * G4 + col0 + 1];
                // interleaved 4k+gate: even lane (i,f), odd lane (g,o)
                float p00 = __shfl_xor_sync(0xffffffffu, v00, 1);
                float p01 = __shfl_xor_sync(0xffffffffu, v01, 1);
                float p10 = __shfl_xor_sync(0xffffffffu, v10, 1);
                float p11 = __shfl_xor_sync(0xffffffffu, v11, 1);
                if ((lane & 1) == 0) {
                    int k = col0 >> 2;
                    float cs0 = d_cst[row0 * HID + k];
                    float cn0 = sigf(v01) * cs0 + sigf(v00) * tanhf_(p00);
                    d_cst[row0 * HID + k] = cn0;
                    Xw[row0 * KXP + k] = __float2half(sigf(p01) * tanhf_(cn0));
                    float cs1 = d_cst[row1 * HID + k];
                    float cn1 = sigf(v11) * cs1 + sigf(v10) * tanhf_(p10);
                    d_cst[row1 * HID + k] = cn1;
                    Xw[row1 * KXP + k] = __float2half(sigf(p11) * tanhf_(cn1));
                }
            } else if (MODE == 1) {
                float b0v = bias[col0], b1v = bias[col0 + 1];
                d_t1[(size_t)row0 * HID + col0    ] = __float2half(fmaxf(v00 + b0v, 0.f));
                d_t1[(size_t)row0 * HID + col0 + 1] = __float2half(fmaxf(v01 + b1v, 0.f));
                d_t1[(size_t)row1 * HID + col0    ] = __float2half(fmaxf(v10 + b0v, 0.f));
                d_t1[(size_t)row1 * HID + col0 + 1] = __float2half(fmaxf(v11 + b1v, 0.f));
            } else {
                #pragma unroll
                for (int e = 0; e < 2; e++) {
                    int col = col0 + e;
                    if (col < OUTD) {
                        float bv = bias[col];
                        float a0 = (e == 0 ? v00 : v01) + bv;
                        float a1 = (e == 0 ? v10 : v11) + bv;
                        outp[((size_t)row0 * SEQL + t) * OUTD + col] = a0;
                        outp[((size_t)row1 * SEQL + t) * OUTD + col] = a1;
                        Xw[row0 * KXP + HID + col] = __float2half(a0);
                        Xw[row1 * KXP + HID + col] = __float2half(a1);
                    }
                }
            }
        }
    }
    __syncthreads();     // stage buffers free before next tile's prologue
}

// ------------------------- persistent kernel -------------------------------
__global__ void __launch_bounds__(NTHREADS)
rnn_persist(const int* __restrict__ labels,
            const float* __restrict__ b_fc1, const float* __restrict__ b_fc2,
            float* __restrict__ out, unsigned nblocks) {
    extern __shared__ __align__(16) char smem[];
    uint32_t sa;
    asm("{ .reg .u64 t; cvta.to.shared.u64 t, %1; cvt.u32.u64 %0, t; }"
        : "=r"(sa) : "l"(smem));
    __shared__ unsigned s_tile;

    unsigned ep = 0;
    const int tid = threadIdx.x;

    auto fetch = [&]() -> unsigned {
        __syncthreads();
        if (tid == 0) s_tile = atomicAdd(&g_ctr[ep & 1023], 1u);
        __syncthreads();
        return s_tile;
    };

    for (int t = 0; t < SEQL; t++) {
        __half* Xcur = d_Xbuf[t & 1];
        __half* Xnxt = d_Xbuf[(t & 1) ^ 1];

        // gates + fused cell: 4m x 64n = 256 tiles of 128x128, K=2240
        for (unsigned tile = fetch(); tile < 256; tile = fetch())
            gemm_tile<0, 128, 128>((tile >> 6) * 128, (tile & 63) * 128, KXP,
                                   Xcur, KXP, Xnxt, labels, nullptr, nullptr,
                                   0, sa);
        grid_sync(nblocks, ep);

        // fc1 + relu: 8m x 16n = 128 tiles of 64x128, K=2048
        for (unsigned tile = fetch(); tile < 128; tile = fetch())
            gemm_tile<1, 64, 128>((tile >> 4) * 64, (tile & 15) * 128, HID,
                                  Xnxt, KXP, nullptr, nullptr, b_fc1, nullptr,
                                  0, sa);
        grid_sync(nblocks, ep);

        // fc2: 8m x 3n = 24 tiles of 64x64, K=2048
        for (unsigned tile = fetch(); tile < 24; tile = fetch())
            gemm_tile<2, 64, 64>((tile / 3) * 64, (tile % 3) * 64, HID,
                                 d_t1, HID, Xnxt, nullptr, b_fc2, out,
                                 t, sa);
        grid_sync(nblocks, ep);
    }
}

// ------------------------- launch ------------------------------------------
extern "C" void kernel_launch(void* const* d_in, const int* in_sizes, int n_in,
                              void* d_out, int out_size) {
    const float* inputs = (const float*)d_in[0];
    const int*   labels = (const int*)  d_in[1];
    const float* W_enc  = (const float*)d_in[3];
    const float* b_enc  = (const float*)d_in[4];
    const float* W_ih   = (const float*)d_in[5];
    const float* b_ih   = (const float*)d_in[6];
    const float* W_hh   = (const float*)d_in[7];
    const float* b_hh   = (const float*)d_in[8];
    const float* W_fc1  = (const float*)d_in[9];
    const float* b_fc1  = (const float*)d_in[10];
    const float* W_fc2  = (const float*)d_in[11];
    const float* b_fc2  = (const float*)d_in[12];
    const float* W_inh  = (const float*)d_in[13];
    const float* b_inh  = (const float*)d_in[14];
    const float* W_inc  = (const float*)d_in[15];
    const float* b_inc  = (const float*)d_in[16];
    float* out = (float*)d_out;

    cudaFuncSetAttribute(rnn_persist,
                         cudaFuncAttributeMaxDynamicSharedMemorySize, SMEM_REQ);

    int dev = 0, sms = 0, occ = 0;
    cudaGetDevice(&dev);
    cudaDeviceGetAttribute(&sms, cudaDevAttrMultiProcessorCount, dev);
    cudaOccupancyMaxActiveBlocksPerMultiprocessor(&occ, rnn_persist, NTHREADS, SMEM_REQ);
    if (occ < 1) occ = 1;
    unsigned nblocks = (unsigned)(sms * occ);

    setup_all<<<SB_TOT, 256>>>(inputs, W_enc, b_enc, W_ih, b_ih, W_hh, b_hh,
                               W_fc1, W_fc2, W_inh, b_inh, W_inc, b_inc);
    rnn_persist<<<nblocks, NTHREADS, SMEM_REQ>>>(labels, b_fc1, b_fc2, out, nblocks);
}

// round 15
// speedup vs baseline: 1.2316x; 1.2316x over previous
#include <cuda_runtime.h>
#include <cuda_fp16.h>
#include <math.h>
#include <stdint.h>

// ---------------------------------------------------------------------------
// DecoderRNN: 240-step LSTM decoder, B=512, H=2048, OUT=165, NCLS=40
// R15: R10 structure (best config) made REPLAY-CLEAN so ncu measures reality:
//  - sense-reversing grid barrier (self-resets g_arrive each epoch)
//  - dynamic tile counters in a 16-slot ring zeroed at kernel entry and
//    re-zeroed 8 epochs ahead of reuse
//  - paired 6-stage cp.async pipeline, phase overlap via d_gacc, fused cell
// ---------------------------------------------------------------------------

#define BATCH   512
#define HID     2048
#define G4      8192
#define OUTD    165
#define NCLS    40
#define SEQL    240
#define WIH_COLS 330
#define KXP     2240        // 2048 (h) + 192 (out_prev pad)
#define NPAD2   192

#define ROWH    40          // smem row stride in halves (32 + 8 pad)
#define NTHREADS 512
#define STAGEB  ((128 + 256) * ROWH * 2)        // 30720 per slab (max shape)
#define SMEM_REQ (6 * STAGEB)                   // 184320

// ------------------------- device scratch ----------------------------------
__device__ __half d_Wcat[(size_t)G4 * KXP];     // interleaved rows n'=4k+g
__device__ __half d_Wfc1[(size_t)HID * HID];
__device__ __half d_Wfc2[(size_t)NPAD2 * HID];
__device__ float  d_gbias[NCLS * G4];           // interleaved cols
__device__ __half d_Xbuf[2][BATCH * KXP];       // ping-pong (h | out_prev)
__device__ float  d_cst[BATCH * HID];
__device__ __half d_t1[BATCH * HID];
__device__ float  d_gacc[(size_t)BATCH * G4];   // gates partial sums (fp32)
__device__ unsigned g_arrive;                   // self-resetting arrivals
__device__ unsigned g_release;                  // monotone release word
__device__ unsigned g_ctr[16];                  // tile-counter ring

// ------------------------- ONE setup kernel --------------------------------
#define NA      71680                       // G4*KXP/256
#define SB_FC1  (NA + 16384)
#define SB_FC2  (SB_FC1 + 1536)
#define SB_GB   (SB_FC2 + NCLS * 32)
#define SB_INIT (SB_GB + BATCH * 8)
#define SB_TOT  (SB_INIT + BATCH)
__global__ void setup_all(const float* __restrict__ inputs,
                          const float* __restrict__ W_enc, const float* __restrict__ b_enc,
                          const float* __restrict__ W_ih,  const float* __restrict__ b_ih,
                          const float* __restrict__ W_hh,  const float* __restrict__ b_hh,
                          const float* __restrict__ W_fc1,
                          const float* __restrict__ W_fc2,
                          const float* __restrict__ W_inh, const float* __restrict__ b_inh,
                          const float* __restrict__ W_inc, const float* __restrict__ b_inc) {
    int bid = blockIdx.x, tid = threadIdx.x;

    if (bid < NA) {
        size_t idx = (size_t)bid * 256 + tid;
        int np = (int)(idx / KXP), k = (int)(idx % KXP);
        int n = (np & 3) * HID + (np >> 2);       // interleave n'=4k+g
        float v = 0.f;
        if (k < HID)             v = W_hh[(size_t)n * HID + k];
        else if (k - HID < OUTD) v = W_ih[(size_t)n * WIH_COLS + (k - HID)];
        d_Wcat[idx] = __float2half(v);
    } else if (bid < SB_FC1) {
        size_t idx = (size_t)(bid - NA) * 256 + tid;
        d_Wfc1[idx] = __float2half(W_fc1[idx]);
    } else if (bid < SB_FC2) {
        size_t idx = (size_t)(bid - SB_FC1) * 256 + tid;
        int n = (int)(idx / HID), k = (int)(idx % HID);
        d_Wfc2[idx] = __float2half(n < OUTD ? W_fc2[(size_t)n * HID + k] : 0.f);
    } else if (bid < SB_GB) {
        int q = bid - SB_FC2;
        int cls = q >> 5;
        int n = (q & 31) * 256 + tid;
        __shared__ float enc[OUTD];
        if (tid < OUTD) enc[tid] = W_enc[tid * NCLS + cls] + b_enc[tid];
        __syncthreads();
        float a = b_ih[n] + b_hh[n];
        const float* wrow = W_ih + (size_t)n * WIH_COLS + OUTD;
        #pragma unroll 5
        for (int j = 0; j < OUTD; j++) a += wrow[j] * enc[j];
        int np = 4 * (n & (HID - 1)) + (n >> 11);
        d_gbias[cls * G4 + np] = a;
    } else if (bid < SB_INIT) {
        int q = bid - SB_GB;
        int b = q >> 3;
        int k = (q & 7) * 256 + tid;
        __shared__ float f0[OUTD];
        if (tid < OUTD) f0[tid] = inputs[b * OUTD + tid];
        __syncthreads();
        float ah = b_inh[k], ac = b_inc[k];
        const float* wh = W_inh + (size_t)k * OUTD;
        const float* wc = W_inc + (size_t)k * OUTD;
        #pragma unroll 5
        for (int j = 0; j < OUTD; j++) { ah += f0[j] * wh[j]; ac += f0[j] * wc[j]; }
        d_cst[b * HID + k] = ac;
        d_Xbuf[0][b * KXP + k] = __float2half(ah);
    } else {
        int b = bid - SB_INIT;
        int j = tid;
        if (j < KXP - HID) {
            float v = (j < OUTD) ? inputs[b * OUTD + j] : 0.f;
            d_Xbuf[0][b * KXP + HID + j] = __float2half(v);
            if (j >= OUTD) d_Xbuf[1][b * KXP + HID + j] = __float2half(0.f);
        }
    }
}

// ------------------------- helpers -----------------------------------------
__device__ __forceinline__ void cpa16(uint32_t s, const void* g) {
    asm volatile("cp.async.cg.shared.global [%0], [%1], 16;" :: "r"(s), "l"(g));
}
__device__ __forceinline__ void cpa_commit() { asm volatile("cp.async.commit_group;"); }
template<int N> __device__ __forceinline__ void cpa_wait() {
    asm volatile("cp.async.wait_group %0;" :: "n"(N));
}
__device__ __forceinline__ float sigf(float x) {
    return __fdividef(1.f, 1.f + __expf(-x));
}
__device__ __forceinline__ float tanhf_(float x) {
    float e = __expf(-2.f * x);
    return __fdividef(1.f - e, 1.f + e);
}
// Sense-reversing, self-resetting grid barrier. g_arrive returns to 0 each
// epoch (last arriver resets), so the kernel is clean on ANY launch/replay.
__device__ __forceinline__ void grid_sync(unsigned nblocks) {
    __syncthreads();
    if (threadIdx.x == 0) {
        __threadfence();
        unsigned rel = *(volatile unsigned*)&g_release;
        unsigned a = atomicAdd(&g_arrive, 1u);
        if (a == nblocks - 1u) {
            g_arrive = 0u;                      // reset for next epoch
            __threadfence();
            atomicAdd(&g_release, 1u);          // release waiters
        } else {
            while (*(volatile unsigned*)&g_release == rel) { __nanosleep(64); }
        }
        __threadfence();
    }
    __syncthreads();
}

// ------------------------- GEMM tile (mma.sync) ----------------------------
// C[BM,BN] = A[BM, kofs:kofs+nk*32] @ B[BN, same]^T. 16 warps (2m x 8n).
// 6-slab pipeline in pairs; one __syncthreads per 2 k-iters.
// MODE 0: gates-finish + gacc + gbias + fused LSTM cell -> Xw h, d_cst
// MODE 1: fc1 + relu+bias -> d_t1
// MODE 2: fc2 + bias -> out & Xw out_prev tail
// MODE 3: gates partial: store acc -> d_gacc
// MODE 4: gates partial: d_gacc += acc
template<int MODE, int BM, int BN>
__device__ void gemm_tile(int m0, int n0, int kofs, int nk,
                          const __half* __restrict__ Ag, int lda,
                          __half* __restrict__ Xw,
                          const int* __restrict__ labels,
                          const float* __restrict__ bias,
                          float* __restrict__ outp, int t,
                          uint32_t sa) {
    constexpr int WMr = BM / 2;
    constexpr int WNr = BN / 8;
    constexpr int MT  = WMr / 16;
    constexpr int NT  = WNr / 8;
    constexpr int CH  = (BM + BN) * 4;   // 16B chunks per stage

    const __half* Bg; int ldb;
    if (MODE == 1)      { Bg = d_Wfc1; ldb = HID; }
    else if (MODE == 2) { Bg = d_Wfc2; ldb = HID; }
    else                { Bg = d_Wcat; ldb = KXP; }

    const int tid  = threadIdx.x;
    const int lane = tid & 31;
    const int wid  = tid >> 5;
    const int wm   = wid & 1;
    const int wn   = wid >> 1;          // 0..7

    float acc[MT][NT][4];
    #pragma unroll
    for (int i = 0; i < MT; i++)
        #pragma unroll
        for (int j = 0; j < NT; j++)
            #pragma unroll
            for (int k = 0; k < 4; k++) acc[i][j][k] = 0.f;

    // load k-slabs kb2, kb2+1 into stages pairSlot*2, pairSlot*2+1
    auto load_pair = [&](int pairSlot, int kb2) {
        #pragma unroll
        for (int j = 0; j < 2; j++) {
            const int ko = kofs + (kb2 + j) * 32;
            const uint32_t base = sa + (uint32_t)((pairSlot * 2 + j) * STAGEB);
            #pragma unroll
            for (int c = tid; c < CH; c += NTHREADS) {
                int row = c >> 2;
                int k8  = (c & 3) * 8;
                if (row < BM)
                    cpa16(base + (uint32_t)((row * ROWH + k8) * 2),
                          Ag + (size_t)(m0 + row) * lda + ko + k8);
                else
                    cpa16(base + (uint32_t)((row * ROWH + k8) * 2),
                          Bg + (size_t)(n0 + row - BM) * ldb + ko + k8);
            }
        }
    };

    // ldmatrix lane bases (stage-relative)
    const uint32_t aOff = (uint32_t)(((wm * WMr + (lane & 15)) * ROWH
                                      + (lane >> 4) * 8) * 2);
    const uint32_t bOff4 = (uint32_t)(((BM + wn * WNr + (lane & 15)) * ROWH
                                       + (lane >> 4) * 8) * 2);
    const uint32_t bOff2 = (uint32_t)(((BM + wn * WNr + (lane & 7)) * ROWH
                                       + ((lane >> 3) & 1) * 8) * 2);

    load_pair(0, 0); cpa_commit();
    load_pair(1, 2); cpa_commit();

    for (int kb = 0; kb < nk; kb += 2) {
        cpa_wait<1>();
        __syncthreads();                    // prior pair's reads all done
        const int pr = (kb >> 1) % 3;
        if (kb + 4 < nk) load_pair((pr + 2) % 3, kb + 4);
        cpa_commit();

        #pragma unroll
        for (int j = 0; j < 2; j++) {
            const uint32_t stb = sa + (uint32_t)((pr * 2 + j) * STAGEB);
            const uint32_t aS = stb + aOff;
            #pragma unroll
            for (int ks = 0; ks < 2; ks++) {
                uint32_t af[MT][4];
                #pragma unroll
                for (int mt = 0; mt < MT; mt++) {
                    uint32_t ad = aS + (uint32_t)((mt * 16 * ROWH + ks * 16) * 2);
                    asm volatile("ldmatrix.sync.aligned.m8n8.x4.shared.b16 "
                                 "{%0,%1,%2,%3}, [%4];"
                                 : "=r"(af[mt][0]), "=r"(af[mt][1]),
                                   "=r"(af[mt][2]), "=r"(af[mt][3]) : "r"(ad));
                }
                uint32_t bb[NT][2];
                if constexpr (NT >= 2) {
                    const uint32_t bS = stb + bOff4;
                    #pragma unroll
                    for (int np = 0; np < NT / 2; np++) {
                        uint32_t bd = bS + (uint32_t)((np * 16 * ROWH + ks * 16) * 2);
                        asm volatile("ldmatrix.sync.aligned.m8n8.x4.shared.b16 "
                                     "{%0,%1,%2,%3}, [%4];"
                                     : "=r"(bb[2*np][0]), "=r"(bb[2*np+1][0]),
                                       "=r"(bb[2*np][1]), "=r"(bb[2*np+1][1]) : "r"(bd));
                    }
                } else {
                    const uint32_t bS = stb + bOff2;
                    uint32_t bd = bS + (uint32_t)((ks * 16) * 2);
                    asm volatile("ldmatrix.sync.aligned.m8n8.x2.shared.b16 "
                                 "{%0,%1}, [%2];"
                                 : "=r"(bb[0][0]), "=r"(bb[0][1]) : "r"(bd));
                }
                #pragma unroll
                for (int nt = 0; nt < NT; nt++) {
                    #pragma unroll
                    for (int mt = 0; mt < MT; mt++) {
                        float* c = acc[mt][nt];
                        asm volatile(
                            "mma.sync.aligned.m16n8k16.row.col.f32.f16.f16.f32 "
                            "{%0,%1,%2,%3}, {%4,%5,%6,%7}, {%8,%9}, {%0,%1,%2,%3};"
                            : "+f"(c[0]), "+f"(c[1]), "+f"(c[2]), "+f"(c[3])
                            : "r"(af[mt][0]), "r"(af[mt][1]),
                              "r"(af[mt][2]), "r"(af[mt][3]),
                              "r"(bb[nt][0]), "r"(bb[nt][1]));
                    }
                }
            }
        }
    }
    cpa_wait<0>();

    // ---------------- epilogue ----------------
    const int r  = lane >> 2;
    const int c2 = (lane & 3) << 1;
    #pragma unroll
    for (int mt = 0; mt < MT; mt++) {
        int row0 = m0 + wm * WMr + mt * 16 + r;
        int row1 = row0 + 8;
        int lb0 = 0, lb1 = 0;
        if (MODE == 0) { lb0 = labels[row0]; lb1 = labels[row1]; }
        #pragma unroll
        for (int nt = 0; nt < NT; nt++) {
            int col0 = n0 + wn * WNr + nt * 8 + c2;
            float v00 = acc[mt][nt][0], v01 = acc[mt][nt][1];
            float v10 = acc[mt][nt][2], v11 = acc[mt][nt][3];
            if (MODE == 3) {
                *(float2*)&d_gacc[(size_t)row0 * G4 + col0] = make_float2(v00, v01);
                *(float2*)&d_gacc[(size_t)row1 * G4 + col0] = make_float2(v10, v11);
            } else if (MODE == 4) {
                float2 a0 = *(float2*)&d_gacc[(size_t)row0 * G4 + col0];
                float2 a1 = *(float2*)&d_gacc[(size_t)row1 * G4 + col0];
                *(float2*)&d_gacc[(size_t)row0 * G4 + col0] =
                    make_float2(v00 + a0.x, v01 + a0.y);
                *(float2*)&d_gacc[(size_t)row1 * G4 + col0] =
                    make_float2(v10 + a1.x, v11 + a1.y);
            } else if (MODE == 0) {
                float2 a0 = *(float2*)&d_gacc[(size_t)row0 * G4 + col0];
                float2 a1 = *(float2*)&d_gacc[(size_t)row1 * G4 + col0];
                v00 += a0.x + d_gbias[lb0 * G4 + col0];
                v01 += a0.y + d_gbias[lb0 * G4 + col0 + 1];
                v10 += a1.x + d_gbias[lb1 * G4 + col0];
                v11 += a1.y + d_gbias[lb1 * G4 + col0 + 1];
                // interleaved 4k+gate: even lane (i,f), odd lane (g,o)
                float p00 = __shfl_xor_sync(0xffffffffu, v00, 1);
                float p01 = __shfl_xor_sync(0xffffffffu, v01, 1);
                float p10 = __shfl_xor_sync(0xffffffffu, v10, 1);
                float p11 = __shfl_xor_sync(0xffffffffu, v11, 1);
                if ((lane & 1) == 0) {
                    int k = col0 >> 2;
                    float cs0 = d_cst[row0 * HID + k];
                    float cn0 = sigf(v01) * cs0 + sigf(v00) * tanhf_(p00);
                    d_cst[row0 * HID + k] = cn0;
                    Xw[row0 * KXP + k] = __float2half(sigf(p01) * tanhf_(cn0));
                    float cs1 = d_cst[row1 * HID + k];
                    float cn1 = sigf(v11) * cs1 + sigf(v10) * tanhf_(p10);
                    d_cst[row1 * HID + k] = cn1;
                    Xw[row1 * KXP + k] = __float2half(sigf(p11) * tanhf_(cn1));
                }
            } else if (MODE == 1) {
                float b0v = bias[col0], b1v = bias[col0 + 1];
                d_t1[(size_t)row0 * HID + col0    ] = __float2half(fmaxf(v00 + b0v, 0.f));
                d_t1[(size_t)row0 * HID + col0 + 1] = __float2half(fmaxf(v01 + b1v, 0.f));
                d_t1[(size_t)row1 * HID + col0    ] = __float2half(fmaxf(v10 + b0v, 0.f));
                d_t1[(size_t)row1 * HID + col0 + 1] = __float2half(fmaxf(v11 + b1v, 0.f));
            } else {
                #pragma unroll
                for (int e = 0; e < 2; e++) {
                    int col = col0 + e;
                    if (col < OUTD) {
                        float bv = bias[col];
                        float a0 = (e == 0 ? v00 : v01) + bv;
                        float a1 = (e == 0 ? v10 : v11) + bv;
                        outp[((size_t)row0 * SEQL + t) * OUTD + col] = a0;
                        outp[((size_t)row1 * SEQL + t) * OUTD + col] = a1;
                        Xw[row0 * KXP + HID + col] = __float2half(a0);
                        Xw[row1 * KXP + HID + col] = __float2half(a1);
                    }
                }
            }
        }
    }
    __syncthreads();     // stage buffers free before next tile's prologue
}

// ------------------------- persistent kernel -------------------------------
__global__ void __launch_bounds__(NTHREADS)
rnn_persist(const int* __restrict__ labels,
            const float* __restrict__ b_fc1, const float* __restrict__ b_fc2,
            float* __restrict__ out, unsigned nblocks) {
    extern __shared__ __align__(16) char smem[];
    uint32_t sa;
    asm("{ .reg .u64 t; cvta.to.shared.u64 t, %1; cvt.u32.u64 %0, t; }"
        : "=r"(sa) : "l"(smem));
    __shared__ unsigned s_tile;

    const int tid = threadIdx.x;
    const unsigned bx = blockIdx.x;
    unsigned ep = 0;

    // entry: block 0 zeroes the counter ring; barrier makes it visible
    if (bx == 0 && tid < 16) g_ctr[tid] = 0;
    grid_sync(nblocks);

    auto fetch = [&]() -> unsigned {
        __syncthreads();
        if (tid == 0) s_tile = atomicAdd(&g_ctr[ep & 15], 1u);
        __syncthreads();
        return s_tile;
    };
    // end one epoch: barrier + re-zero slot 8 ahead (safe: 8-epoch guard)
    auto next_epoch = [&]() {
        grid_sync(nblocks);
        if (bx == 0 && tid == 0) g_ctr[(ep + 8) & 15] = 0;
        ep++;
    };

    // ---- P0 bootstrap: d_gacc = Wh . h0  (K=2048, 128 tiles) ----
    for (unsigned tile = fetch(); tile < 128; tile = fetch())
        gemm_tile<3, 128, 256>((tile >> 5) * 128, (tile & 31) * 256, 0, 64,
                               d_Xbuf[0], KXP, nullptr, nullptr, nullptr,
                               nullptr, 0, sa);
    next_epoch();

    for (int t = 0; t < SEQL; t++) {
        __half* Xcur = d_Xbuf[t & 1];
        __half* Xnxt = d_Xbuf[(t & 1) ^ 1];

        // ---- P1: gates-finish (K=192 out_prev slice) + cell: 128 tiles ----
        for (unsigned tile = fetch(); tile < 128; tile = fetch())
            gemm_tile<0, 128, 256>((tile >> 5) * 128, (tile & 31) * 256,
                                   HID, 6, Xcur, KXP, Xnxt, labels,
                                   nullptr, nullptr, 0, sa);
        next_epoch();

        // ---- P2: gates K[0:1024) partial (128) || fc1 (64 tiles 64x128x2048? -> 128 of 64x128) ----
        for (unsigned tile = fetch(); tile < 256; tile = fetch()) {
            if (tile < 128)
                gemm_tile<3, 128, 256>((tile >> 5) * 128, (tile & 31) * 256,
                                       0, 32, Xnxt, KXP, nullptr, nullptr,
                                       nullptr, nullptr, 0, sa);
            else {
                unsigned f = tile - 128;
                gemm_tile<1, 64, 128>((f >> 4) * 64, (f & 15) * 128,
                                      0, 64, Xnxt, KXP, nullptr, nullptr,
                                      b_fc1, nullptr, 0, sa);
            }
        }
        next_epoch();

        // ---- P3: gates K[1024:2048) accum (128) || fc2 (24) ----
        for (unsigned tile = fetch(); tile < 152; tile = fetch()) {
            if (tile < 128)
                gemm_tile<4, 128, 256>((tile >> 5) * 128, (tile & 31) * 256,
                                       1024, 32, Xnxt, KXP, nullptr, nullptr,
                                       nullptr, nullptr, 0, sa);
            else {
                unsigned f = tile - 128;
                gemm_tile<2, 64, 64>((f / 3) * 64, (f % 3) * 64,
                                     0, 64, d_t1, HID, Xnxt, nullptr,
                                     b_fc2, out, t, sa);
            }
        }
        next_epoch();
    }
}

// ------------------------- launch ------------------------------------------
extern "C" void kernel_launch(void* const* d_in, const int* in_sizes, int n_in,
                              void* d_out, int out_size) {
    const float* inputs = (const float*)d_in[0];
    const int*   labels = (const int*)  d_in[1];
    const float* W_enc  = (const float*)d_in[3];
    const float* b_enc  = (const float*)d_in[4];
    const float* W_ih   = (const float*)d_in[5];
    const float* b_ih   = (const float*)d_in[6];
    const float* W_hh   = (const float*)d_in[7];
    const float* b_hh   = (const float*)d_in[8];
    const float* W_fc1  = (const float*)d_in[9];
    const float* b_fc1  = (const float*)d_in[10];
    const float* W_fc2  = (const float*)d_in[11];
    const float* b_fc2  = (const float*)d_in[12];
    const float* W_inh  = (const float*)d_in[13];
    const float* b_inh  = (const float*)d_in[14];
    const float* W_inc  = (const float*)d_in[15];
    const float* b_inc  = (const float*)d_in[16];
    float* out = (float*)d_out;

    cudaFuncSetAttribute(rnn_persist,
                         cudaFuncAttributeMaxDynamicSharedMemorySize, SMEM_REQ);

    int dev = 0, sms = 0, occ = 0;
    cudaGetDevice(&dev);
    cudaDeviceGetAttribute(&sms, cudaDevAttrMultiProcessorCount, dev);
    cudaOccupancyMaxActiveBlocksPerMultiprocessor(&occ, rnn_persist, NTHREADS, SMEM_REQ);
    if (occ < 1) occ = 1;
    unsigned nblocks = (unsigned)(sms * occ);

    setup_all<<<SB_TOT, 256>>>(inputs, W_enc, b_enc, W_ih, b_ih, W_hh, b_hh,
                               W_fc1, W_fc2, W_inh, b_inh, W_inc, b_inc);
    rnn_persist<<<nblocks, NTHREADS, SMEM_REQ>>>(labels, b_fc1, b_fc2, out, nblocks);
}